// round 1
// baseline (speedup 1.0000x reference)
#include <cuda_runtime.h>
#include <math.h>

#define LSEQ 1024
#define BATCH 8
#define HDIM 300
#define NC 11234   // number of band pairs |j-i|<=5 for L=1024
#define W1COLS 650

// ---------------- device scratch (static allocation, allowed) ----------------
__device__ float g_A[BATCH * LSEQ * HDIM];   // (h_e+h_share) @ W1[:,0:300]^T
__device__ float g_C[BATCH * LSEQ * HDIM];   // (h_c+h_share) @ W1[:,300:600]^T
__device__ float g_T2[11 * HDIM];            // rel-pos term projected + b1 folded
__device__ int   g_ii[NC];
__device__ int   g_jj[NC];

// ---------------- band index precompute ----------------
__global__ void init_idx_kernel() {
    int i = blockIdx.x * blockDim.x + threadIdx.x;
    if (i >= LSEQ) return;
    int off;
    if (i <= 1019) off = (i < 5) ? (i * i + 11 * i) / 2 : 11 * i - 15;
    else { int s = i - 1019; off = 11194 + 10 * s - s * (s - 1) / 2; }
    int jlo = i - 5 < 0 ? 0 : i - 5;
    int jhi = i + 5 > LSEQ - 1 ? LSEQ - 1 : i + 5;
    for (int j = jlo; j <= jhi; ++j) {
        g_ii[off] = i;
        g_jj[off] = j;
        ++off;
    }
}

// ---------------- T2[r,h] = b1[h] + sum_d ( sum_r' cnt(r')*exp(-(r-r')^2)*pos_W[r',d] ) * W1[h,600+d]
__global__ void table_kernel(const float* __restrict__ posW,
                             const float* __restrict__ W1,
                             const float* __restrict__ b1) {
    int idx = blockIdx.x * blockDim.x + threadIdx.x;
    if (idx >= 11 * HDIM) return;
    int r = idx / HDIM;
    int h = idx % HDIM;
    float w[11];
#pragma unroll
    for (int rp = 0; rp < 11; rp++) {
        float d = (float)(r - rp);
        int a = rp - 5; if (a < 0) a = -a;
        w[rp] = (float)(LSEQ - a) * expf(-d * d);
    }
    float acc = b1[h];
    const float* w1row = W1 + h * W1COLS + 600;
#pragma unroll 2
    for (int d = 0; d < 50; d++) {
        float tv = 0.f;
#pragma unroll
        for (int rp = 0; rp < 11; rp++) tv += w[rp] * posW[rp * 50 + d];
        acc += tv * w1row[d];
    }
    g_T2[idx] = acc;
}

// ---------------- tiled fp32 SGEMM: [8192,300] x W1-slice^T -> [8192,300]
// blockIdx.z = 0: X = h_e+h_share, W1[:,0:300]   -> g_A
// blockIdx.z = 1: X = h_c+h_share, W1[:,300:600] -> g_C
#define TBM 64
#define TBN 64
#define TBK 20

__global__ __launch_bounds__(256) void gemm_kernel(
    const float* __restrict__ h_e, const float* __restrict__ h_c,
    const float* __restrict__ h_share, const float* __restrict__ W1)
{
    __shared__ __align__(16) float As[TBK][TBM];
    __shared__ __align__(16) float Bs[TBK][TBN];

    const int z = blockIdx.z;
    const float* X = z ? h_c : h_e;
    const int off = z ? 300 : 0;
    float* Out = z ? g_C : g_A;

    const int m0 = blockIdx.y * TBM;
    const int n0 = blockIdx.x * TBN;
    const int tid = threadIdx.x;
    const int tx = tid & 15;
    const int ty = tid >> 4;

    float acc[4][4] = {};

    for (int k0 = 0; k0 < HDIM; k0 += TBK) {
        // load X tile (64 rows x 20 k) with the h_share add fused
#pragma unroll
        for (int e = 0; e < 5; e++) {
            int idx = tid + e * 256;
            int r = idx / TBK, c = idx % TBK;
            int g = (m0 + r) * HDIM + k0 + c;
            As[c][r] = X[g] + h_share[g];
        }
        // load W1 tile (64 n x 20 k), zero-pad n >= 300
#pragma unroll
        for (int e = 0; e < 5; e++) {
            int idx = tid + e * 256;
            int n = idx / TBK, c = idx % TBK;
            int gn = n0 + n;
            Bs[c][n] = (gn < HDIM) ? W1[gn * W1COLS + off + k0 + c] : 0.f;
        }
        __syncthreads();
#pragma unroll
        for (int kk = 0; kk < TBK; kk++) {
            float4 a4 = *(const float4*)&As[kk][ty * 4];
            float4 b4 = *(const float4*)&Bs[kk][tx * 4];
            float av[4] = {a4.x, a4.y, a4.z, a4.w};
            float bw[4] = {b4.x, b4.y, b4.z, b4.w};
#pragma unroll
            for (int r = 0; r < 4; r++)
#pragma unroll
                for (int c = 0; c < 4; c++)
                    acc[r][c] += av[r] * bw[c];
        }
        __syncthreads();
    }

#pragma unroll
    for (int r = 0; r < 4; r++) {
        int gm = m0 + ty * 4 + r;
#pragma unroll
        for (int c = 0; c < 4; c++) {
            int gn = n0 + tx * 4 + c;
            if (gn < HDIM) Out[gm * HDIM + gn] = acc[r][c];
        }
    }
}

// ---------------- fused epilogue: gather + LayerNorm + ELU + dot(W2) ----------------
// one warp per (b, pair)
__global__ __launch_bounds__(256) void epi_kernel(
    const float* __restrict__ lng, const float* __restrict__ lnb,
    const float* __restrict__ W2, const float* __restrict__ b2,
    float* __restrict__ out, int write_pos)
{
    const int warp = threadIdx.x >> 5;
    const int lane = threadIdx.x & 31;
    const int pg = blockIdx.x * 8 + warp;
    if (pg >= BATCH * NC) return;
    const int b = pg / NC;
    const int p = pg - b * NC;
    const int i = g_ii[p];
    const int j = g_jj[p];
    const int r = j - i + 5;

    const float* Arow = g_A + (b * LSEQ + i) * HDIM;
    const float* Crow = g_C + (b * LSEQ + j) * HDIM;
    const float* Trow = g_T2 + r * HDIM;

    float v[10];
    float s1 = 0.f, s2 = 0.f;
#pragma unroll
    for (int it = 0; it < 10; it++) {
        int h = lane + it * 32;
        float x = 0.f;
        if (h < HDIM) x = Arow[h] + Crow[h] + Trow[h];
        v[it] = x;
        s1 += x;
        s2 += x * x;
    }
#pragma unroll
    for (int o = 16; o; o >>= 1) {
        s1 += __shfl_xor_sync(0xffffffffu, s1, o);
        s2 += __shfl_xor_sync(0xffffffffu, s2, o);
    }
    const float inv = 1.f / (float)HDIM;
    float mu = s1 * inv;
    float var = s2 * inv - mu * mu;
    float rstd = rsqrtf(var + 1e-5f);

    float dot = 0.f;
#pragma unroll
    for (int it = 0; it < 10; it++) {
        int h = lane + it * 32;
        if (h < HDIM) {
            float y = (v[it] - mu) * rstd * __ldg(lng + h) + __ldg(lnb + h);
            y = (y > 0.f) ? y : expm1f(y);
            dot += y * __ldg(W2 + h);
        }
    }
#pragma unroll
    for (int o = 16; o; o >>= 1) dot += __shfl_xor_sync(0xffffffffu, dot, o);

    if (lane == 0) out[b * NC + p] = dot + __ldg(b2);
    if (write_pos && b == 0 && lane == 0) {
        out[BATCH * NC + 2 * p]     = (float)(i + 1);
        out[BATCH * NC + 2 * p + 1] = (float)(j + 1);
    }
}

// ---------------- launcher ----------------
extern "C" void kernel_launch(void* const* d_in, const int* in_sizes, int n_in,
                              void* d_out, int out_size) {
    const float* h_e     = (const float*)d_in[0];
    const float* h_c     = (const float*)d_in[1];
    const float* h_share = (const float*)d_in[2];
    // d_in[3] = mask (unused by the forward body)
    const float* pos_W   = (const float*)d_in[4];
    const float* W1      = (const float*)d_in[5];
    const float* b1      = (const float*)d_in[6];
    const float* ln_g    = (const float*)d_in[7];
    const float* ln_b    = (const float*)d_in[8];
    const float* W2      = (const float*)d_in[9];
    const float* b2      = (const float*)d_in[10];
    float* out = (float*)d_out;

    init_idx_kernel<<<4, 256>>>();
    table_kernel<<<(11 * HDIM + 255) / 256, 256>>>(pos_W, W1, b1);

    dim3 ggrid((HDIM + TBN - 1) / TBN, (BATCH * LSEQ) / TBM, 2);
    gemm_kernel<<<ggrid, 256>>>(h_e, h_c, h_share, W1);

    int write_pos = (out_size >= BATCH * NC + 2 * NC) ? 1 : 0;
    epi_kernel<<<(BATCH * NC + 7) / 8, 256>>>(ln_g, ln_b, W2, b2, out, write_pos);
}

// round 2
// speedup vs baseline: 1.9716x; 1.9716x over previous
#include <cuda_runtime.h>
#include <math.h>

#define LSEQ 1024
#define BATCH 8
#define HDIM 300
#define NC 11234   // number of band pairs |j-i|<=5 for L=1024
#define W1COLS 650

// ---------------- device scratch ----------------
__device__ float g_A[BATCH * LSEQ * HDIM];   // (h_e+h_share) @ W1[:,0:300]^T
__device__ float g_C[BATCH * LSEQ * HDIM];   // (h_c+h_share) @ W1[:,300:600]^T
__device__ float g_T2[11 * HDIM];            // rel-pos term + b1 folded
__device__ int   g_ii[NC];
__device__ int   g_jj[NC];

// ---------------- band index precompute ----------------
__global__ void init_idx_kernel() {
    int i = blockIdx.x * blockDim.x + threadIdx.x;
    if (i >= LSEQ) return;
    int off;
    if (i <= 1019) off = (i < 5) ? (i * i + 11 * i) / 2 : 11 * i - 15;
    else { int s = i - 1019; off = 11194 + 10 * s - s * (s - 1) / 2; }
    int jlo = i - 5 < 0 ? 0 : i - 5;
    int jhi = i + 5 > LSEQ - 1 ? LSEQ - 1 : i + 5;
    for (int j = jlo; j <= jhi; ++j) {
        g_ii[off] = i;
        g_jj[off] = j;
        ++off;
    }
}

// ---------------- T2 table ----------------
__global__ void table_kernel(const float* __restrict__ posW,
                             const float* __restrict__ W1,
                             const float* __restrict__ b1) {
    int idx = blockIdx.x * blockDim.x + threadIdx.x;
    if (idx >= 11 * HDIM) return;
    int r = idx / HDIM;
    int h = idx % HDIM;
    float w[11];
#pragma unroll
    for (int rp = 0; rp < 11; rp++) {
        float d = (float)(r - rp);
        int a = rp - 5; if (a < 0) a = -a;
        w[rp] = (float)(LSEQ - a) * expf(-d * d);
    }
    float acc = b1[h];
    const float* w1row = W1 + h * W1COLS + 600;
#pragma unroll 2
    for (int d = 0; d < 50; d++) {
        float tv = 0.f;
#pragma unroll
        for (int rp = 0; rp < 11; rp++) tv += w[rp] * posW[rp * 50 + d];
        acc += tv * w1row[d];
    }
    g_T2[idx] = acc;
}

// ---------------- tf32 tensor-core GEMM ----------------
// [8192,300] x W1-slice^T -> [8192,300], z=0 -> g_A (h_e), z=1 -> g_C (h_c)
// Block tile 128x64, 8 warps of 32x32, mma m16n8k8 tf32, fp32 accum.
#define GBM 128
#define GBN 64
#define GBK 16

__device__ __forceinline__ unsigned f2tf(float x) {
    unsigned u;
    asm("cvt.rna.tf32.f32 %0, %1;" : "=r"(u) : "f"(x));
    return u;
}

// smem k-position swizzle: within a 16-k tile, k -> (k>>3)*8 + 2*(k&3) + ((k>>2)&1)
// so (k, k+4) are adjacent -> one LDS.64 per fragment pair.
__device__ __forceinline__ int kpos(int k) {
    return ((k >> 3) << 3) + 2 * (k & 3) + ((k >> 2) & 1);
}

__global__ __launch_bounds__(256) void gemm_tf32_kernel(
    const float* __restrict__ h_e, const float* __restrict__ h_c,
    const float* __restrict__ h_share, const float* __restrict__ W1)
{
    __shared__ __align__(16) unsigned As[GBM][20];  // [m][swizzled k], stride 20 = 2-phase LDS.64
    __shared__ __align__(16) unsigned Bs[GBN][20];  // [n][swizzled k]

    const int z = blockIdx.z;
    const float* X = z ? h_c : h_e;
    const int off = z ? 300 : 0;
    float* Out = z ? g_C : g_A;

    const int m0 = blockIdx.y * GBM;
    const int n0 = blockIdx.x * GBN;
    const int tid = threadIdx.x;
    const int warp = tid >> 5;
    const int lane = tid & 31;
    const int wm = (warp & 3) * 32;   // warp m offset in block
    const int wn = (warp >> 2) * 32;  // warp n offset in block
    const int lq = lane >> 2;         // 0..7
    const int lr = lane & 3;          // 0..3

    float acc[2][4][4];
#pragma unroll
    for (int a = 0; a < 2; a++)
#pragma unroll
        for (int b = 0; b < 4; b++)
#pragma unroll
            for (int c = 0; c < 4; c++) acc[a][b][c] = 0.f;

    for (int k0 = 0; k0 < HDIM; k0 += GBK) {
        // ---- load A tile 128 x 16 (X + h_share, cvt tf32, swizzled) ----
#pragma unroll
        for (int rep = 0; rep < 2; rep++) {
            int m = (tid >> 2) + rep * 64;
            int c4 = tid & 3;
            int k = k0 + c4 * 4;
            int base = (c4 >> 1) * 8 + (c4 & 1);   // kpos(4*c4 + e) = base + 2e
            if (k < HDIM) {  // 300 - k0 is a multiple of 4, so whole float4 valid
                const float4 xv = *(const float4*)&X[(m0 + m) * HDIM + k];
                const float4 sv = *(const float4*)&h_share[(m0 + m) * HDIM + k];
                As[m][base + 0] = f2tf(xv.x + sv.x);
                As[m][base + 2] = f2tf(xv.y + sv.y);
                As[m][base + 4] = f2tf(xv.z + sv.z);
                As[m][base + 6] = f2tf(xv.w + sv.w);
            } else {
                As[m][base + 0] = 0u; As[m][base + 2] = 0u;
                As[m][base + 4] = 0u; As[m][base + 6] = 0u;
            }
        }
        // ---- load B tile 64 x 16 (W1 slice, cvt tf32, swizzled) ----
#pragma unroll
        for (int rep = 0; rep < 2; rep++) {
            int n = (tid >> 3) + rep * 32;
            int c2 = tid & 7;
            int gn = n0 + n;
            int kl = 2 * c2;
            float2 wv = make_float2(0.f, 0.f);
            if (gn < HDIM && (k0 + kl) < HDIM)
                wv = *(const float2*)&W1[gn * W1COLS + off + k0 + kl];
            Bs[n][kpos(kl)]     = f2tf(wv.x);
            Bs[n][kpos(kl + 1)] = f2tf(wv.y);
        }
        __syncthreads();

#pragma unroll
        for (int s = 0; s < 2; s++) {
            unsigned af[2][4];
#pragma unroll
            for (int mf = 0; mf < 2; mf++) {
                int mrow = wm + mf * 16 + lq;
                uint2 lo = *(const uint2*)&As[mrow][s * 8 + 2 * lr];
                uint2 hi = *(const uint2*)&As[mrow + 8][s * 8 + 2 * lr];
                af[mf][0] = lo.x; af[mf][2] = lo.y;
                af[mf][1] = hi.x; af[mf][3] = hi.y;
            }
            unsigned bf[4][2];
#pragma unroll
            for (int nf = 0; nf < 4; nf++) {
                int nrow = wn + nf * 8 + lq;
                uint2 bv = *(const uint2*)&Bs[nrow][s * 8 + 2 * lr];
                bf[nf][0] = bv.x; bf[nf][1] = bv.y;
            }
#pragma unroll
            for (int mf = 0; mf < 2; mf++)
#pragma unroll
                for (int nf = 0; nf < 4; nf++) {
                    asm volatile(
                        "mma.sync.aligned.m16n8k8.row.col.f32.tf32.tf32.f32 "
                        "{%0,%1,%2,%3}, {%4,%5,%6,%7}, {%8,%9}, {%0,%1,%2,%3};\n"
                        : "+f"(acc[mf][nf][0]), "+f"(acc[mf][nf][1]),
                          "+f"(acc[mf][nf][2]), "+f"(acc[mf][nf][3])
                        : "r"(af[mf][0]), "r"(af[mf][1]), "r"(af[mf][2]), "r"(af[mf][3]),
                          "r"(bf[nf][0]), "r"(bf[nf][1]));
                }
        }
        __syncthreads();
    }

    // ---- store ----
#pragma unroll
    for (int mf = 0; mf < 2; mf++) {
        int row = m0 + wm + mf * 16 + lq;
#pragma unroll
        for (int nf = 0; nf < 4; nf++) {
            int col = n0 + wn + nf * 8 + 2 * lr;
            if (col < HDIM) {
                *(float2*)&Out[row * HDIM + col] =
                    make_float2(acc[mf][nf][0], acc[mf][nf][1]);
                *(float2*)&Out[(row + 8) * HDIM + col] =
                    make_float2(acc[mf][nf][2], acc[mf][nf][3]);
            }
        }
    }
}

// ---------------- fused epilogue: gather + LayerNorm + ELU + dot(W2) ----------------
// one warp per (b, pair); float4 gathers; params cached in smem
__global__ __launch_bounds__(256) void epi_kernel(
    const float* __restrict__ lng, const float* __restrict__ lnb,
    const float* __restrict__ W2, const float* __restrict__ b2,
    float* __restrict__ out, int write_pos)
{
    __shared__ __align__(16) float s_g[304];
    __shared__ __align__(16) float s_b[304];
    __shared__ __align__(16) float s_w[304];
    for (int h = threadIdx.x; h < HDIM; h += 256) {
        s_g[h] = lng[h]; s_b[h] = lnb[h]; s_w[h] = W2[h];
    }
    __syncthreads();

    const int warp = threadIdx.x >> 5;
    const int lane = threadIdx.x & 31;
    const int pg = blockIdx.x * 8 + warp;
    if (pg >= BATCH * NC) return;
    const int b = pg / NC;
    const int p = pg - b * NC;
    const int i = g_ii[p];
    const int j = g_jj[p];
    const int r = j - i + 5;

    const float4* A4 = (const float4*)(g_A + (b * LSEQ + i) * HDIM);
    const float4* C4 = (const float4*)(g_C + (b * LSEQ + j) * HDIM);
    const float4* T4 = (const float4*)(g_T2 + r * HDIM);

    float4 v[3];
    float s1 = 0.f, s2 = 0.f;
#pragma unroll
    for (int it = 0; it < 3; it++) {
        int f = it * 32 + lane;            // 75 float4 = 300 floats
        float4 x = make_float4(0.f, 0.f, 0.f, 0.f);
        if (f < 75) {
            float4 a = A4[f], c = C4[f], t = T4[f];
            x.x = a.x + c.x + t.x; x.y = a.y + c.y + t.y;
            x.z = a.z + c.z + t.z; x.w = a.w + c.w + t.w;
        }
        v[it] = x;
        s1 += x.x + x.y + x.z + x.w;
        s2 += x.x * x.x + x.y * x.y + x.z * x.z + x.w * x.w;
    }
#pragma unroll
    for (int o = 16; o; o >>= 1) {
        s1 += __shfl_xor_sync(0xffffffffu, s1, o);
        s2 += __shfl_xor_sync(0xffffffffu, s2, o);
    }
    const float inv = 1.f / (float)HDIM;
    float mu = s1 * inv;
    float var = s2 * inv - mu * mu;
    float rstd = rsqrtf(var + 1e-5f);

    float dot = 0.f;
#pragma unroll
    for (int it = 0; it < 3; it++) {
        int f = it * 32 + lane;
        if (f < 75) {
            float4 g = *(const float4*)&s_g[f * 4];
            float4 bb = *(const float4*)&s_b[f * 4];
            float4 w = *(const float4*)&s_w[f * 4];
            float xe[4] = {v[it].x, v[it].y, v[it].z, v[it].w};
            float ge[4] = {g.x, g.y, g.z, g.w};
            float be[4] = {bb.x, bb.y, bb.z, bb.w};
            float we[4] = {w.x, w.y, w.z, w.w};
#pragma unroll
            for (int e = 0; e < 4; e++) {
                float y = (xe[e] - mu) * rstd * ge[e] + be[e];
                y = (y > 0.f) ? y : (__expf(y) - 1.f);
                dot += y * we[e];
            }
        }
    }
#pragma unroll
    for (int o = 16; o; o >>= 1) dot += __shfl_xor_sync(0xffffffffu, dot, o);

    if (lane == 0) out[b * NC + p] = dot + __ldg(b2);
    if (write_pos && b == 0 && lane == 0) {
        out[BATCH * NC + 2 * p]     = (float)(i + 1);
        out[BATCH * NC + 2 * p + 1] = (float)(j + 1);
    }
}

// ---------------- launcher ----------------
extern "C" void kernel_launch(void* const* d_in, const int* in_sizes, int n_in,
                              void* d_out, int out_size) {
    const float* h_e     = (const float*)d_in[0];
    const float* h_c     = (const float*)d_in[1];
    const float* h_share = (const float*)d_in[2];
    const float* pos_W   = (const float*)d_in[4];
    const float* W1      = (const float*)d_in[5];
    const float* b1      = (const float*)d_in[6];
    const float* ln_g    = (const float*)d_in[7];
    const float* ln_b    = (const float*)d_in[8];
    const float* W2      = (const float*)d_in[9];
    const float* b2      = (const float*)d_in[10];
    float* out = (float*)d_out;

    init_idx_kernel<<<4, 256>>>();
    table_kernel<<<(11 * HDIM + 255) / 256, 256>>>(pos_W, W1, b1);

    dim3 ggrid((HDIM + GBN - 1) / GBN, (BATCH * LSEQ) / GBM, 2);
    gemm_tf32_kernel<<<ggrid, 256>>>(h_e, h_c, h_share, W1);

    int write_pos = (out_size >= BATCH * NC + 2 * NC) ? 1 : 0;
    epi_kernel<<<(BATCH * NC + 7) / 8, 256>>>(ln_g, ln_b, W2, b2, out, write_pos);
}

// round 4
// speedup vs baseline: 2.6945x; 1.3667x over previous
#include <cuda_runtime.h>
#include <math.h>
#include <stdint.h>

#define LSEQ 1024
#define BATCH 8
#define HDIM 300
#define NC 11234
#define W1COLS 650
#define NPAIR (BATCH * NC)

// ---------------- device scratch ----------------
__device__ float g_A[BATCH * LSEQ * HDIM];
__device__ float g_C[BATCH * LSEQ * HDIM];
__device__ float g_He[BATCH * LSEQ * HDIM];
__device__ float g_Hc[BATCH * LSEQ * HDIM];
__device__ float g_T2[11 * HDIM];
__device__ int   g_ii[NC];
__device__ int   g_jj[NC];

// ---------------- elementwise pre-pass: He = h_e+h_share, Hc = h_c+h_share ----
__global__ __launch_bounds__(256) void add_kernel(
    const float* __restrict__ h_e, const float* __restrict__ h_c,
    const float* __restrict__ h_share)
{
    const int N4 = BATCH * LSEQ * HDIM / 4;   // 614400
    int t = blockIdx.x * 256 + threadIdx.x;
    if (t >= N4) return;
    float4 s = ((const float4*)h_share)[t];
    float4 a = ((const float4*)h_e)[t];
    float4 c = ((const float4*)h_c)[t];
    a.x += s.x; a.y += s.y; a.z += s.z; a.w += s.w;
    c.x += s.x; c.y += s.y; c.z += s.z; c.w += s.w;
    ((float4*)g_He)[t] = a;
    ((float4*)g_Hc)[t] = c;
}

// ---------------- init: band indices + T2 table ----------------
__global__ void init_kernel(const float* __restrict__ posW,
                            const float* __restrict__ W1,
                            const float* __restrict__ b1) {
    int gid = blockIdx.x * blockDim.x + threadIdx.x;
    if (gid < LSEQ) {
        int i = gid;
        int off;
        if (i <= 1019) off = (i < 5) ? (i * i + 11 * i) / 2 : 11 * i - 15;
        else { int s = i - 1019; off = 11194 + 10 * s - s * (s - 1) / 2; }
        int jlo = i - 5 < 0 ? 0 : i - 5;
        int jhi = i + 5 > LSEQ - 1 ? LSEQ - 1 : i + 5;
        for (int j = jlo; j <= jhi; ++j) { g_ii[off] = i; g_jj[off] = j; ++off; }
    }
    if (gid < 11 * HDIM) {
        int r = gid / HDIM;
        int h = gid % HDIM;
        float w[11];
#pragma unroll
        for (int rp = 0; rp < 11; rp++) {
            float d = (float)(r - rp);
            int a = rp - 5; if (a < 0) a = -a;
            w[rp] = (float)(LSEQ - a) * expf(-d * d);
        }
        float acc = b1[h];
        const float* w1row = W1 + h * W1COLS + 600;
#pragma unroll 2
        for (int d = 0; d < 50; d++) {
            float tv = 0.f;
#pragma unroll
            for (int rp = 0; rp < 11; rp++) tv += w[rp] * posW[rp * 50 + d];
            acc += tv * w1row[d];
        }
        g_T2[gid] = acc;
    }
}

// ---------------- cp.async pipelined tf32 GEMM ----------------
// [8192,300] x W1-slice^T -> [8192,300]; z=0: g_He -> g_A, z=1: g_Hc -> g_C
#define GBM 128
#define GBN 64
#define GBK 16
#define KSTR 20          // smem row stride in words (conflict-free pattern)
#define NIT 19           // ceil(300/16)

__device__ __forceinline__ void cp_async16(uint32_t dst, const void* src, int src_bytes) {
    asm volatile("cp.async.cg.shared.global [%0], [%1], 16, %2;\n"
                 :: "r"(dst), "l"(src), "r"(src_bytes));
}
__device__ __forceinline__ void cp_async8(uint32_t dst, const void* src, int src_bytes) {
    asm volatile("cp.async.ca.shared.global [%0], [%1], 8, %2;\n"
                 :: "r"(dst), "l"(src), "r"(src_bytes));
}

__global__ __launch_bounds__(256) void gemm_tf32_kernel(const float* __restrict__ W1)
{
    __shared__ __align__(16) float As[2][GBM][KSTR];
    __shared__ __align__(16) float Bs[2][GBN][KSTR];

    const int z = blockIdx.z;
    const float* X = z ? g_Hc : g_He;
    const int off = z ? 300 : 0;
    float* Out = z ? g_C : g_A;

    const int m0 = blockIdx.y * GBM;
    const int n0 = blockIdx.x * GBN;
    const int tid = threadIdx.x;
    const int warp = tid >> 5;
    const int lane = tid & 31;
    const int wm = (warp & 3) * 32;
    const int wn = (warp >> 2) * 32;
    const int lq = lane >> 2;
    const int lr = lane & 3;

    // copy geometry: A = 512 x 16B chunks, B = 512 x 8B chunks, 2 per thread
    const int arow = tid >> 2;              // 0..63 (+64 for chunk 2)
    const int ak   = (tid & 3) * 4;         // k within tile: 0,4,8,12
    const int brow = tid >> 3;              // 0..31 (+32 for chunk 2)
    const int bk   = (tid & 7) * 2;         // k within tile: 0..14 even

    const float* aSrc0 = X + (m0 + arow) * HDIM + ak;
    const float* aSrc1 = X + (m0 + arow + 64) * HDIM + ak;
    const float* bSrc0 = W1 + (n0 + brow) * W1COLS + off + bk;
    const float* bSrc1 = W1 + (n0 + brow + 32) * W1COLS + off + bk;
    const bool bOk0 = (n0 + brow) < HDIM;
    const bool bOk1 = (n0 + brow + 32) < HDIM;

    const uint32_t aD0 = (uint32_t)__cvta_generic_to_shared(&As[0][arow][ak]);
    const uint32_t aD1 = (uint32_t)__cvta_generic_to_shared(&As[0][arow + 64][ak]);
    const uint32_t bD0 = (uint32_t)__cvta_generic_to_shared(&Bs[0][brow][bk]);
    const uint32_t bD1 = (uint32_t)__cvta_generic_to_shared(&Bs[0][brow + 32][bk]);
    const uint32_t aBufSz = GBM * KSTR * 4;   // 10240
    const uint32_t bBufSz = GBN * KSTR * 4;   // 5120

    float acc[2][4][4];
#pragma unroll
    for (int a = 0; a < 2; a++)
#pragma unroll
        for (int b = 0; b < 4; b++)
#pragma unroll
            for (int c = 0; c < 4; c++) acc[a][b][c] = 0.f;

    auto issue = [&](int stage, int k0) {
        int asz = ((k0 + ak) < HDIM) ? 16 : 0;
        cp_async16(aD0 + stage * aBufSz, aSrc0 + k0, asz);
        cp_async16(aD1 + stage * aBufSz, aSrc1 + k0, asz);
        bool kOk = (k0 + bk) < HDIM;
        cp_async8(bD0 + stage * bBufSz, bSrc0 + k0, (bOk0 && kOk) ? 8 : 0);
        cp_async8(bD1 + stage * bBufSz, bSrc1 + k0, (bOk1 && kOk) ? 8 : 0);
    };

    issue(0, 0);
    asm volatile("cp.async.commit_group;\n" ::: "memory");

    for (int it = 0; it < NIT; it++) {
        const int buf = it & 1;
        if (it + 1 < NIT) issue(buf ^ 1, (it + 1) * GBK);
        asm volatile("cp.async.commit_group;\n" ::: "memory");
        asm volatile("cp.async.wait_group 1;\n" ::: "memory");
        __syncthreads();

#pragma unroll
        for (int s = 0; s < 2; s++) {
            const int kb = s * 8 + lr;
            unsigned af[2][4];
#pragma unroll
            for (int mf = 0; mf < 2; mf++) {
                const int mrow = wm + mf * 16 + lq;
                af[mf][0] = __float_as_uint(As[buf][mrow][kb]);
                af[mf][1] = __float_as_uint(As[buf][mrow + 8][kb]);
                af[mf][2] = __float_as_uint(As[buf][mrow][kb + 4]);
                af[mf][3] = __float_as_uint(As[buf][mrow + 8][kb + 4]);
            }
            unsigned bf[4][2];
#pragma unroll
            for (int nf = 0; nf < 4; nf++) {
                const int nrow = wn + nf * 8 + lq;
                bf[nf][0] = __float_as_uint(Bs[buf][nrow][kb]);
                bf[nf][1] = __float_as_uint(Bs[buf][nrow][kb + 4]);
            }
#pragma unroll
            for (int mf = 0; mf < 2; mf++)
#pragma unroll
                for (int nf = 0; nf < 4; nf++) {
                    asm volatile(
                        "mma.sync.aligned.m16n8k8.row.col.f32.tf32.tf32.f32 "
                        "{%0,%1,%2,%3}, {%4,%5,%6,%7}, {%8,%9}, {%0,%1,%2,%3};\n"
                        : "+f"(acc[mf][nf][0]), "+f"(acc[mf][nf][1]),
                          "+f"(acc[mf][nf][2]), "+f"(acc[mf][nf][3])
                        : "r"(af[mf][0]), "r"(af[mf][1]), "r"(af[mf][2]), "r"(af[mf][3]),
                          "r"(bf[nf][0]), "r"(bf[nf][1]));
                }
        }
        __syncthreads();
    }

#pragma unroll
    for (int mf = 0; mf < 2; mf++) {
        const int row = m0 + wm + mf * 16 + lq;
#pragma unroll
        for (int nf = 0; nf < 4; nf++) {
            const int col = n0 + wn + nf * 8 + 2 * lr;
            if (col < HDIM) {
                *(float2*)&Out[row * HDIM + col] =
                    make_float2(acc[mf][nf][0], acc[mf][nf][1]);
                *(float2*)&Out[(row + 8) * HDIM + col] =
                    make_float2(acc[mf][nf][2], acc[mf][nf][3]);
            }
        }
    }
}

// ---------------- fused epilogue: 2 pairs per warp ----------------
__global__ __launch_bounds__(256) void epi_kernel(
    const float* __restrict__ lng, const float* __restrict__ lnb,
    const float* __restrict__ W2, const float* __restrict__ b2,
    float* __restrict__ out, int write_pos)
{
    __shared__ __align__(16) float s_g[304];
    __shared__ __align__(16) float s_b[304];
    __shared__ __align__(16) float s_w[304];
    for (int h = threadIdx.x; h < HDIM; h += 256) {
        s_g[h] = lng[h]; s_b[h] = lnb[h]; s_w[h] = W2[h];
    }
    __syncthreads();

    const int warp = threadIdx.x >> 5;
    const int lane = threadIdx.x & 31;
    const int pg0 = (blockIdx.x * 8 + warp) * 2;
    if (pg0 >= NPAIR) return;

    int pb[2], pp[2], pi[2], pj[2];
    bool valid[2];
#pragma unroll
    for (int u = 0; u < 2; u++) {
        int pg = pg0 + u;
        valid[u] = (pg < NPAIR);
        int pgc = valid[u] ? pg : 0;
        pb[u] = pgc / NC;
        pp[u] = pgc - pb[u] * NC;
        pi[u] = g_ii[pp[u]];
        pj[u] = g_jj[pp[u]];
    }

    float4 v[2][3];
    float s1[2] = {0.f, 0.f}, s2[2] = {0.f, 0.f};
#pragma unroll
    for (int u = 0; u < 2; u++) {
        const float4* A4 = (const float4*)(g_A + (pb[u] * LSEQ + pi[u]) * HDIM);
        const float4* C4 = (const float4*)(g_C + (pb[u] * LSEQ + pj[u]) * HDIM);
        const float4* T4 = (const float4*)(g_T2 + (pj[u] - pi[u] + 5) * HDIM);
#pragma unroll
        for (int it = 0; it < 3; it++) {
            int f = it * 32 + lane;
            float4 x = make_float4(0.f, 0.f, 0.f, 0.f);
            if (f < 75) {
                float4 a = A4[f], c = C4[f], t = T4[f];
                x.x = a.x + c.x + t.x; x.y = a.y + c.y + t.y;
                x.z = a.z + c.z + t.z; x.w = a.w + c.w + t.w;
            }
            v[u][it] = x;
            s1[u] += x.x + x.y + x.z + x.w;
            s2[u] += x.x * x.x + x.y * x.y + x.z * x.z + x.w * x.w;
        }
    }
#pragma unroll
    for (int o = 16; o; o >>= 1) {
#pragma unroll
        for (int u = 0; u < 2; u++) {
            s1[u] += __shfl_xor_sync(0xffffffffu, s1[u], o);
            s2[u] += __shfl_xor_sync(0xffffffffu, s2[u], o);
        }
    }
    const float inv = 1.f / (float)HDIM;
    float mu[2], rstd[2], dot[2] = {0.f, 0.f};
#pragma unroll
    for (int u = 0; u < 2; u++) {
        mu[u] = s1[u] * inv;
        float var = s2[u] * inv - mu[u] * mu[u];
        rstd[u] = rsqrtf(var + 1e-5f);
    }

#pragma unroll
    for (int it = 0; it < 3; it++) {
        int f = it * 32 + lane;
        if (f < 75) {
            float4 g = *(const float4*)&s_g[f * 4];
            float4 bb = *(const float4*)&s_b[f * 4];
            float4 w = *(const float4*)&s_w[f * 4];
            float ge[4] = {g.x, g.y, g.z, g.w};
            float be[4] = {bb.x, bb.y, bb.z, bb.w};
            float we[4] = {w.x, w.y, w.z, w.w};
#pragma unroll
            for (int u = 0; u < 2; u++) {
                float xe[4] = {v[u][it].x, v[u][it].y, v[u][it].z, v[u][it].w};
#pragma unroll
                for (int e = 0; e < 4; e++) {
                    float y = (xe[e] - mu[u]) * rstd[u] * ge[e] + be[e];
                    y = (y > 0.f) ? y : (__expf(y) - 1.f);
                    dot[u] += y * we[e];
                }
            }
        }
    }
#pragma unroll
    for (int o = 16; o; o >>= 1) {
#pragma unroll
        for (int u = 0; u < 2; u++)
            dot[u] += __shfl_xor_sync(0xffffffffu, dot[u], o);
    }

    if (lane == 0) {
        float bias = __ldg(b2);
#pragma unroll
        for (int u = 0; u < 2; u++) {
            if (valid[u]) {
                out[pb[u] * NC + pp[u]] = dot[u] + bias;
                if (write_pos && pb[u] == 0) {
                    out[NPAIR + 2 * pp[u]]     = (float)(pi[u] + 1);
                    out[NPAIR + 2 * pp[u] + 1] = (float)(pj[u] + 1);
                }
            }
        }
    }
}

// ---------------- launcher ----------------
extern "C" void kernel_launch(void* const* d_in, const int* in_sizes, int n_in,
                              void* d_out, int out_size) {
    const float* h_e     = (const float*)d_in[0];
    const float* h_c     = (const float*)d_in[1];
    const float* h_share = (const float*)d_in[2];
    const float* pos_W   = (const float*)d_in[4];
    const float* W1      = (const float*)d_in[5];
    const float* b1      = (const float*)d_in[6];
    const float* ln_g    = (const float*)d_in[7];
    const float* ln_b    = (const float*)d_in[8];
    const float* W2      = (const float*)d_in[9];
    const float* b2      = (const float*)d_in[10];
    float* out = (float*)d_out;

    const int N4 = BATCH * LSEQ * HDIM / 4;
    add_kernel<<<(N4 + 255) / 256, 256>>>(h_e, h_c, h_share);
    init_kernel<<<(11 * HDIM + 255) / 256, 256>>>(pos_W, W1, b1);

    dim3 ggrid((HDIM + GBN - 1) / GBN, (BATCH * LSEQ) / GBM, 2);
    gemm_tf32_kernel<<<ggrid, 256>>>(W1);

    int write_pos = (out_size >= NPAIR + 2 * NC) ? 1 : 0;
    int warps_needed = (NPAIR + 1) / 2;
    epi_kernel<<<(warps_needed + 7) / 8, 256>>>(ln_g, ln_b, W2, b2, out, write_pos);
}

// round 5
// speedup vs baseline: 2.7310x; 1.0136x over previous
#include <cuda_runtime.h>
#include <math.h>
#include <stdint.h>

#define LSEQ 1024
#define BATCH 8
#define HDIM 300
#define NC 11234
#define W1COLS 650
#define NPAIR (BATCH * NC)

// ---------------- device scratch ----------------
__device__ float g_A[BATCH * LSEQ * HDIM];
__device__ float g_C[BATCH * LSEQ * HDIM];
__device__ float g_He[BATCH * LSEQ * HDIM];
__device__ float g_Hc[BATCH * LSEQ * HDIM];
__device__ float g_T2[11 * HDIM];
__device__ int   g_ii[NC];
__device__ int   g_jj[NC];

// ---------------- elementwise pre-pass ----------------
__global__ __launch_bounds__(256) void add_kernel(
    const float* __restrict__ h_e, const float* __restrict__ h_c,
    const float* __restrict__ h_share)
{
    const int N4 = BATCH * LSEQ * HDIM / 4;
    int t = blockIdx.x * 256 + threadIdx.x;
    if (t >= N4) return;
    float4 s = ((const float4*)h_share)[t];
    float4 a = ((const float4*)h_e)[t];
    float4 c = ((const float4*)h_c)[t];
    a.x += s.x; a.y += s.y; a.z += s.z; a.w += s.w;
    c.x += s.x; c.y += s.y; c.z += s.z; c.w += s.w;
    ((float4*)g_He)[t] = a;
    ((float4*)g_Hc)[t] = c;
}

// ---------------- init: band indices + T2 table ----------------
__global__ void init_kernel(const float* __restrict__ posW,
                            const float* __restrict__ W1,
                            const float* __restrict__ b1) {
    int gid = blockIdx.x * blockDim.x + threadIdx.x;
    if (gid < LSEQ) {
        int i = gid;
        int off;
        if (i <= 1019) off = (i < 5) ? (i * i + 11 * i) / 2 : 11 * i - 15;
        else { int s = i - 1019; off = 11194 + 10 * s - s * (s - 1) / 2; }
        int jlo = i - 5 < 0 ? 0 : i - 5;
        int jhi = i + 5 > LSEQ - 1 ? LSEQ - 1 : i + 5;
        for (int j = jlo; j <= jhi; ++j) { g_ii[off] = i; g_jj[off] = j; ++off; }
    }
    if (gid < 11 * HDIM) {
        int r = gid / HDIM;
        int h = gid % HDIM;
        float w[11];
#pragma unroll
        for (int rp = 0; rp < 11; rp++) {
            float d = (float)(r - rp);
            int a = rp - 5; if (a < 0) a = -a;
            w[rp] = (float)(LSEQ - a) * expf(-d * d);
        }
        float acc = b1[h];
        const float* w1row = W1 + h * W1COLS + 600;
#pragma unroll 2
        for (int d = 0; d < 50; d++) {
            float tv = 0.f;
#pragma unroll
            for (int rp = 0; rp < 11; rp++) tv += w[rp] * posW[rp * 50 + d];
            acc += tv * w1row[d];
        }
        g_T2[gid] = acc;
    }
}

// ---------------- 3-stage cp.async pipelined tf32 GEMM ----------------
#define GBM 128
#define GBN 64
#define GBK 16
#define KSTR 20
#define NIT 19
#define NSTG 3

__device__ __forceinline__ void cp_async16(uint32_t dst, const void* src, int src_bytes) {
    asm volatile("cp.async.cg.shared.global [%0], [%1], 16, %2;\n"
                 :: "r"(dst), "l"(src), "r"(src_bytes));
}
__device__ __forceinline__ void cp_async8(uint32_t dst, const void* src, int src_bytes) {
    asm volatile("cp.async.ca.shared.global [%0], [%1], 8, %2;\n"
                 :: "r"(dst), "l"(src), "r"(src_bytes));
}

__global__ __launch_bounds__(256) void gemm_tf32_kernel(const float* __restrict__ W1)
{
    __shared__ __align__(16) float As[NSTG][GBM][KSTR];   // 30720 B
    __shared__ __align__(16) float Bs[NSTG][GBN][KSTR];   // 15360 B

    const int z = blockIdx.z;
    const float* X = z ? g_Hc : g_He;
    const int off = z ? 300 : 0;
    float* Out = z ? g_C : g_A;

    const int m0 = blockIdx.y * GBM;
    const int n0 = blockIdx.x * GBN;
    const int tid = threadIdx.x;
    const int warp = tid >> 5;
    const int lane = tid & 31;
    const int wm = (warp & 3) * 32;
    const int wn = (warp >> 2) * 32;
    const int lq = lane >> 2;
    const int lr = lane & 3;

    const int arow = tid >> 2;
    const int ak   = (tid & 3) * 4;
    const int brow = tid >> 3;
    const int bk   = (tid & 7) * 2;

    const float* aSrc0 = X + (m0 + arow) * HDIM + ak;
    const float* aSrc1 = X + (m0 + arow + 64) * HDIM + ak;
    const float* bSrc0 = W1 + (n0 + brow) * W1COLS + off + bk;
    const float* bSrc1 = W1 + (n0 + brow + 32) * W1COLS + off + bk;
    const bool bOk0 = (n0 + brow) < HDIM;
    const bool bOk1 = (n0 + brow + 32) < HDIM;

    const uint32_t aD0 = (uint32_t)__cvta_generic_to_shared(&As[0][arow][ak]);
    const uint32_t aD1 = (uint32_t)__cvta_generic_to_shared(&As[0][arow + 64][ak]);
    const uint32_t bD0 = (uint32_t)__cvta_generic_to_shared(&Bs[0][brow][bk]);
    const uint32_t bD1 = (uint32_t)__cvta_generic_to_shared(&Bs[0][brow + 32][bk]);
    const uint32_t aBufSz = GBM * KSTR * 4;
    const uint32_t bBufSz = GBN * KSTR * 4;

    float acc[2][4][4];
#pragma unroll
    for (int a = 0; a < 2; a++)
#pragma unroll
        for (int b = 0; b < 4; b++)
#pragma unroll
            for (int c = 0; c < 4; c++) acc[a][b][c] = 0.f;

    auto issue = [&](int stage, int k0) {
        int asz = ((k0 + ak) < HDIM) ? 16 : 0;
        cp_async16(aD0 + stage * aBufSz, aSrc0 + k0, asz);
        cp_async16(aD1 + stage * aBufSz, aSrc1 + k0, asz);
        bool kOk = (k0 + bk) < HDIM;
        cp_async8(bD0 + stage * bBufSz, bSrc0 + k0, (bOk0 && kOk) ? 8 : 0);
        cp_async8(bD1 + stage * bBufSz, bSrc1 + k0, (bOk1 && kOk) ? 8 : 0);
    };

    issue(0, 0);
    asm volatile("cp.async.commit_group;\n" ::: "memory");
    issue(1, GBK);
    asm volatile("cp.async.commit_group;\n" ::: "memory");

    int buf = 0;
    for (int it = 0; it < NIT; it++) {
        asm volatile("cp.async.wait_group 1;\n" ::: "memory");
        __syncthreads();

        // prefetch stage it+2 (its buffer was released by the sync above)
        int nx = it + 2;
        int nstage = nx % NSTG;
        if (nx < NIT) issue(nstage, nx * GBK);
        asm volatile("cp.async.commit_group;\n" ::: "memory");

#pragma unroll
        for (int s = 0; s < 2; s++) {
            const int kb = s * 8 + lr;
            unsigned af[2][4];
#pragma unroll
            for (int mf = 0; mf < 2; mf++) {
                const int mrow = wm + mf * 16 + lq;
                af[mf][0] = __float_as_uint(As[buf][mrow][kb]);
                af[mf][1] = __float_as_uint(As[buf][mrow + 8][kb]);
                af[mf][2] = __float_as_uint(As[buf][mrow][kb + 4]);
                af[mf][3] = __float_as_uint(As[buf][mrow + 8][kb + 4]);
            }
            unsigned bf[4][2];
#pragma unroll
            for (int nf = 0; nf < 4; nf++) {
                const int nrow = wn + nf * 8 + lq;
                bf[nf][0] = __float_as_uint(Bs[buf][nrow][kb]);
                bf[nf][1] = __float_as_uint(Bs[buf][nrow][kb + 4]);
            }
#pragma unroll
            for (int mf = 0; mf < 2; mf++)
#pragma unroll
                for (int nf = 0; nf < 4; nf++) {
                    asm volatile(
                        "mma.sync.aligned.m16n8k8.row.col.f32.tf32.tf32.f32 "
                        "{%0,%1,%2,%3}, {%4,%5,%6,%7}, {%8,%9}, {%0,%1,%2,%3};\n"
                        : "+f"(acc[mf][nf][0]), "+f"(acc[mf][nf][1]),
                          "+f"(acc[mf][nf][2]), "+f"(acc[mf][nf][3])
                        : "r"(af[mf][0]), "r"(af[mf][1]), "r"(af[mf][2]), "r"(af[mf][3]),
                          "r"(bf[nf][0]), "r"(bf[nf][1]));
                }
        }
        buf = (buf + 1 == NSTG) ? 0 : buf + 1;
    }

#pragma unroll
    for (int mf = 0; mf < 2; mf++) {
        const int row = m0 + wm + mf * 16 + lq;
#pragma unroll
        for (int nf = 0; nf < 4; nf++) {
            const int col = n0 + wn + nf * 8 + 2 * lr;
            if (col < HDIM) {
                *(float2*)&Out[row * HDIM + col] =
                    make_float2(acc[mf][nf][0], acc[mf][nf][1]);
                *(float2*)&Out[(row + 8) * HDIM + col] =
                    make_float2(acc[mf][nf][2], acc[mf][nf][3]);
            }
        }
    }
}

// ---------------- fused epilogue: 2 pairs/warp, recompute pass 2 ----------------
__global__ __launch_bounds__(256) void epi_kernel(
    const float* __restrict__ lng, const float* __restrict__ lnb,
    const float* __restrict__ W2, const float* __restrict__ b2,
    float* __restrict__ out, int write_pos)
{
    __shared__ __align__(16) float s_g[304];
    __shared__ __align__(16) float s_b[304];
    __shared__ __align__(16) float s_w[304];
    for (int h = threadIdx.x; h < HDIM; h += 256) {
        s_g[h] = lng[h]; s_b[h] = lnb[h]; s_w[h] = W2[h];
    }
    __syncthreads();

    const int warp = threadIdx.x >> 5;
    const int lane = threadIdx.x & 31;
    const int pg0 = (blockIdx.x * 8 + warp) * 2;
    if (pg0 >= NPAIR) return;

    int pb[2], pp[2], pi[2], pj[2];
    bool valid[2];
    const float4* A4[2];
    const float4* C4[2];
    const float4* T4[2];
#pragma unroll
    for (int u = 0; u < 2; u++) {
        int pg = pg0 + u;
        valid[u] = (pg < NPAIR);
        int pgc = valid[u] ? pg : 0;
        pb[u] = pgc / NC;
        pp[u] = pgc - pb[u] * NC;
        pi[u] = g_ii[pp[u]];
        pj[u] = g_jj[pp[u]];
        A4[u] = (const float4*)(g_A + (pb[u] * LSEQ + pi[u]) * HDIM);
        C4[u] = (const float4*)(g_C + (pb[u] * LSEQ + pj[u]) * HDIM);
        T4[u] = (const float4*)(g_T2 + (pj[u] - pi[u] + 5) * HDIM);
    }

    // pass 1: moments
    float s1[2] = {0.f, 0.f}, s2[2] = {0.f, 0.f};
#pragma unroll
    for (int it = 0; it < 3; it++) {
        int f = it * 32 + lane;
        if (f < 75) {
#pragma unroll
            for (int u = 0; u < 2; u++) {
                float4 a = A4[u][f], c = C4[u][f], t = T4[u][f];
                float x0 = a.x + c.x + t.x, x1 = a.y + c.y + t.y;
                float x2 = a.z + c.z + t.z, x3 = a.w + c.w + t.w;
                s1[u] += x0 + x1 + x2 + x3;
                s2[u] += x0 * x0 + x1 * x1 + x2 * x2 + x3 * x3;
            }
        }
    }
#pragma unroll
    for (int o = 16; o; o >>= 1) {
#pragma unroll
        for (int u = 0; u < 2; u++) {
            s1[u] += __shfl_xor_sync(0xffffffffu, s1[u], o);
            s2[u] += __shfl_xor_sync(0xffffffffu, s2[u], o);
        }
    }
    const float inv = 1.f / (float)HDIM;
    float mu[2], rstd[2], dot[2] = {0.f, 0.f};
#pragma unroll
    for (int u = 0; u < 2; u++) {
        mu[u] = s1[u] * inv;
        float var = s2[u] * inv - mu[u] * mu[u];
        rstd[u] = rsqrtf(var + 1e-5f);
    }

    // pass 2: recompute x from L1-hot lines, LN+ELU+dot
#pragma unroll
    for (int it = 0; it < 3; it++) {
        int f = it * 32 + lane;
        if (f < 75) {
            float4 g = *(const float4*)&s_g[f * 4];
            float4 bb = *(const float4*)&s_b[f * 4];
            float4 w = *(const float4*)&s_w[f * 4];
            float ge[4] = {g.x, g.y, g.z, g.w};
            float be[4] = {bb.x, bb.y, bb.z, bb.w};
            float we[4] = {w.x, w.y, w.z, w.w};
#pragma unroll
            for (int u = 0; u < 2; u++) {
                float4 a = A4[u][f], c = C4[u][f], t = T4[u][f];
                float xe[4] = {a.x + c.x + t.x, a.y + c.y + t.y,
                               a.z + c.z + t.z, a.w + c.w + t.w};
#pragma unroll
                for (int e = 0; e < 4; e++) {
                    float y = (xe[e] - mu[u]) * rstd[u] * ge[e] + be[e];
                    y = (y > 0.f) ? y : (__expf(y) - 1.f);
                    dot[u] += y * we[e];
                }
            }
        }
    }
#pragma unroll
    for (int o = 16; o; o >>= 1) {
#pragma unroll
        for (int u = 0; u < 2; u++)
            dot[u] += __shfl_xor_sync(0xffffffffu, dot[u], o);
    }

    if (lane == 0) {
        float bias = __ldg(b2);
#pragma unroll
        for (int u = 0; u < 2; u++) {
            if (valid[u]) {
                out[pb[u] * NC + pp[u]] = dot[u] + bias;
                if (write_pos && pb[u] == 0) {
                    out[NPAIR + 2 * pp[u]]     = (float)(pi[u] + 1);
                    out[NPAIR + 2 * pp[u] + 1] = (float)(pj[u] + 1);
                }
            }
        }
    }
}

// ---------------- launcher ----------------
extern "C" void kernel_launch(void* const* d_in, const int* in_sizes, int n_in,
                              void* d_out, int out_size) {
    const float* h_e     = (const float*)d_in[0];
    const float* h_c     = (const float*)d_in[1];
    const float* h_share = (const float*)d_in[2];
    const float* pos_W   = (const float*)d_in[4];
    const float* W1      = (const float*)d_in[5];
    const float* b1      = (const float*)d_in[6];
    const float* ln_g    = (const float*)d_in[7];
    const float* ln_b    = (const float*)d_in[8];
    const float* W2      = (const float*)d_in[9];
    const float* b2      = (const float*)d_in[10];
    float* out = (float*)d_out;

    const int N4 = BATCH * LSEQ * HDIM / 4;
    add_kernel<<<(N4 + 255) / 256, 256>>>(h_e, h_c, h_share);
    init_kernel<<<(11 * HDIM + 255) / 256, 256>>>(pos_W, W1, b1);

    dim3 ggrid((HDIM + GBN - 1) / GBN, (BATCH * LSEQ) / GBM, 2);
    gemm_tf32_kernel<<<ggrid, 256>>>(W1);

    int write_pos = (out_size >= NPAIR + 2 * NC) ? 1 : 0;
    int warps_needed = (NPAIR + 1) / 2;
    epi_kernel<<<(warps_needed + 7) / 8, 256>>>(ln_g, ln_b, W2, b2, out, write_pos);
}